// round 1
// baseline (speedup 1.0000x reference)
#include <cuda_runtime.h>

// LIF recurrence: input [B=32, T=8, C=128, H=32, W=32] fp32, output spikes same shape.
// mem = 0.5*mem + x_t; s = (mem - 1.0 > 0); mem *= (1 - s).
//
// One thread owns 4 contiguous spatial elements (float4) of one batch item and
// iterates the T=8 recurrence with membrane state in registers. Per-timestep
// accesses are warp-contiguous -> fully coalesced 128B transactions.

#define TAU  0.5f
#define V_TH 1.0f

__global__ void __launch_bounds__(256)
lif_kernel(const float4* __restrict__ x, float4* __restrict__ out,
           int chw4, int T)
{
    // global index over B * (CHW/4)
    int idx = blockIdx.x * blockDim.x + threadIdx.x;
    int b = idx / chw4;           // batch
    int s = idx - b * chw4;       // spatial float4 index within CHW

    long base = (long)b * T * chw4 + s;
    const float4* xp = x + base;
    float4* op = out + base;

    float m0 = 0.f, m1 = 0.f, m2 = 0.f, m3 = 0.f;

    #pragma unroll
    for (int t = 0; t < 8; t++) {
        float4 v = xp[(long)t * chw4];
        m0 = fmaf(TAU, m0, v.x);
        m1 = fmaf(TAU, m1, v.y);
        m2 = fmaf(TAU, m2, v.z);
        m3 = fmaf(TAU, m3, v.w);

        float s0 = (m0 - V_TH > 0.f) ? 1.f : 0.f;
        float s1 = (m1 - V_TH > 0.f) ? 1.f : 0.f;
        float s2 = (m2 - V_TH > 0.f) ? 1.f : 0.f;
        float s3 = (m3 - V_TH > 0.f) ? 1.f : 0.f;

        float4 sp = make_float4(s0, s1, s2, s3);
        op[(long)t * chw4] = sp;

        // reset where spiked
        m0 = (s0 > 0.f) ? 0.f : m0;
        m1 = (s1 > 0.f) ? 0.f : m1;
        m2 = (s2 > 0.f) ? 0.f : m2;
        m3 = (s3 > 0.f) ? 0.f : m3;
    }
}

extern "C" void kernel_launch(void* const* d_in, const int* in_sizes, int n_in,
                              void* d_out, int out_size)
{
    const float* x = (const float*)d_in[0];
    float* out = (float*)d_out;

    // Shapes fixed by the problem: [32, 8, 128, 32, 32]
    const int B = 32, T = 8, CHW = 128 * 32 * 32;   // 131072
    const int chw4 = CHW / 4;                       // 32768
    const int total = B * chw4;                     // 1,048,576 threads

    const int threads = 256;
    const int blocks = (total + threads - 1) / threads;

    lif_kernel<<<blocks, threads>>>((const float4*)x, (float4*)out, chw4, T);
}

// round 2
// speedup vs baseline: 1.0162x; 1.0162x over previous
#include <cuda_runtime.h>

// LIF recurrence: input [B=32, T=8, C=128, H=32, W=32] fp32, output spikes same shape.
// mem = 0.5*mem + x_t; s = (mem - 1.0 > 0); mem *= (1 - s).
//
// R2 change: front-batch all T=8 float4 loads into registers BEFORE the
// recurrence, so each thread has 8 outstanding DRAM loads (MLP=8) instead of a
// rolled load->compute->store chain. Compute + stores happen after the loads
// are in flight / landed.

#define TAU  0.5f
#define V_TH 1.0f

#define CHW4  32768   // (128*32*32)/4
#define CHW4_SHIFT 15
#define CHW4_MASK  32767
#define T_STEPS 8

__global__ void __launch_bounds__(256)
lif_kernel(const float4* __restrict__ x, float4* __restrict__ out)
{
    int idx = blockIdx.x * blockDim.x + threadIdx.x;
    int b = idx >> CHW4_SHIFT;        // batch
    int s = idx & CHW4_MASK;          // spatial float4 index within CHW

    long base = ((long)b * T_STEPS) * CHW4 + s;
    const float4* xp = x + base;
    float4* op = out + base;

    // Front-batched loads: 8 independent LDG.128 in flight per thread.
    float4 v[T_STEPS];
    #pragma unroll
    for (int t = 0; t < T_STEPS; t++) {
        v[t] = xp[t * CHW4];
    }

    float m0 = 0.f, m1 = 0.f, m2 = 0.f, m3 = 0.f;

    #pragma unroll
    for (int t = 0; t < T_STEPS; t++) {
        m0 = fmaf(TAU, m0, v[t].x);
        m1 = fmaf(TAU, m1, v[t].y);
        m2 = fmaf(TAU, m2, v[t].z);
        m3 = fmaf(TAU, m3, v[t].w);

        float s0 = (m0 - V_TH > 0.f) ? 1.f : 0.f;
        float s1 = (m1 - V_TH > 0.f) ? 1.f : 0.f;
        float s2 = (m2 - V_TH > 0.f) ? 1.f : 0.f;
        float s3 = (m3 - V_TH > 0.f) ? 1.f : 0.f;

        op[t * CHW4] = make_float4(s0, s1, s2, s3);

        m0 = (s0 > 0.f) ? 0.f : m0;
        m1 = (s1 > 0.f) ? 0.f : m1;
        m2 = (s2 > 0.f) ? 0.f : m2;
        m3 = (s3 > 0.f) ? 0.f : m3;
    }
}

extern "C" void kernel_launch(void* const* d_in, const int* in_sizes, int n_in,
                              void* d_out, int out_size)
{
    const float* x = (const float*)d_in[0];
    float* out = (float*)d_out;

    const int total = 32 * CHW4;            // B * CHW/4 = 1,048,576 threads
    const int threads = 256;
    const int blocks = total / threads;     // 4096

    lif_kernel<<<blocks, threads>>>((const float4*)x, (float4*)out);
}